// round 3
// baseline (speedup 1.0000x reference)
#include <cuda_runtime.h>
#include <math.h>

// Problem constants (fixed shapes: x is (8,1,64,64) float32)
#define B_DIM 8
#define H_DIM 64
#define W_DIM 64
#define N_PIX (H_DIM * W_DIM)          // 4096
#define M0_CONST 0.01f

// Offset table: all (dy,dx) in [-63,63]^2 sorted by d2 = dy^2+dx^2 via
// compile-time counting sort. Packed: d2<<16 | (dy+63)<<8 | (dx+63).
#define NOFF (127 * 127)               // 16129
#define MAXD2 (63 * 63 * 2)            // 7938

struct OffTable { unsigned int v[NOFF]; };

constexpr OffTable make_table() {
    OffTable t{};
    int bins[MAXD2 + 1] = {};
    for (int dy = -63; dy <= 63; ++dy)
        for (int dx = -63; dx <= 63; ++dx)
            bins[dy * dy + dx * dx]++;
    int acc = 0;
    for (int d = 0; d <= MAXD2; ++d) { int c = bins[d]; bins[d] = acc; acc += c; }
    for (int dy = -63; dy <= 63; ++dy)
        for (int dx = -63; dx <= 63; ++dx) {
            int d2 = dy * dy + dx * dx;
            t.v[bins[d2]++] = ((unsigned)d2 << 16)
                            | ((unsigned)(dy + 63) << 8)
                            | (unsigned)(dx + 63);
        }
    return t;
}

__device__ constexpr OffTable g_off = make_table();

// One block = 256 pixels of one batch image. Whole image staged in smem.
__global__ __launch_bounds__(256) void dtm_kernel(const float* __restrict__ xin,
                                                  float* __restrict__ out) {
    __shared__ float simg[N_PIX];      // 16 KB: full 64x64 image
    __shared__ float sred[256];        // block reduction scratch

    const int tid   = threadIdx.x;
    const int batch = blockIdx.x >> 4;           // 16 blocks per batch
    const int base  = (blockIdx.x & 15) << 8;    // pixel slab start
    const float* img = xin + batch * N_PIX;

    // Cooperative load of the full image + partial sum for total mass.
    float part = 0.0f;
    #pragma unroll
    for (int j = 0; j < N_PIX / 256; ++j) {
        float v = img[tid + j * 256];
        simg[tid + j * 256] = v;
        part += v;
    }
    sred[tid] = part;
    __syncthreads();

    // Block tree reduction for total mass.
    #pragma unroll
    for (int s = 128; s > 0; s >>= 1) {
        if (tid < s) sred[tid] += sred[tid + s];
        __syncthreads();
    }
    const float total = sred[0];
    const float m     = M0_CONST * total;

    const int i = base + tid;          // pixel index within image
    const int y = i >> 6;
    const int x = i & 63;

    float result = 0.0f;
    if (total > 0.0f) {
        float cum = 0.0f;
        float s   = 0.0f;
        for (int k = 0; k < NOFF; ++k) {
            const unsigned p = g_off.v[k];           // broadcast load
            const int ny = y + (int)((p >> 8) & 255u) - 63;
            const int nx = x + (int)(p & 255u) - 63;
            if ((unsigned)ny < (unsigned)H_DIM && (unsigned)nx < (unsigned)W_DIM) {
                const float w   = simg[(ny << 6) | nx];
                const float rem = m - cum;           // > 0 while loop runs
                const float eff = fminf(w, rem);
                s   = fmaf(eff, (float)(p >> 16), s);
                cum += w;
                if (cum >= m) break;
            }
        }
        result = sqrtf(s / m);
    }
    out[batch * N_PIX + i] = result;
}

extern "C" void kernel_launch(void* const* d_in, const int* in_sizes, int n_in,
                              void* d_out, int out_size) {
    const float* xin = (const float*)d_in[0];
    float* out = (float*)d_out;
    (void)in_sizes; (void)n_in; (void)out_size;
    dtm_kernel<<<B_DIM * (N_PIX / 256), 256>>>(xin, out);
}

// round 5
// speedup vs baseline: 1.8836x; 1.8836x over previous
#include <cuda_runtime.h>
#include <math.h>

// Problem constants (fixed shapes: x is (8,1,64,64) float32)
#define B_DIM 8
#define H_DIM 64
#define W_DIM 64
#define N_PIX (H_DIM * W_DIM)          // 4096
#define M0_CONST 0.01f

// Offset table: all (dy,dx) in [-63,63]^2 sorted by d2 = dy^2+dx^2 via
// compile-time counting sort. Packed: d2<<16 | (dy+63)<<8 | (dx+63).
#define NOFF (127 * 127)               // 16129
#define MAXD2 (63 * 63 * 2)            // 7938
#define STAGE 2048                     // staged prefix of the table (covers d2 <= ~650)
#define CH 8                           // chunk size (branchless inner unroll)

struct OffTable { unsigned int v[NOFF]; };

constexpr OffTable make_table() {
    OffTable t{};
    int bins[MAXD2 + 1] = {};
    for (int dy = -63; dy <= 63; ++dy)
        for (int dx = -63; dx <= 63; ++dx)
            bins[dy * dy + dx * dx]++;
    int acc = 0;
    for (int d = 0; d <= MAXD2; ++d) { int c = bins[d]; bins[d] = acc; acc += c; }
    for (int dy = -63; dy <= 63; ++dy)
        for (int dx = -63; dx <= 63; ++dx) {
            int d2 = dy * dy + dx * dx;
            t.v[bins[d2]++] = ((unsigned)d2 << 16)
                            | ((unsigned)(dy + 63) << 8)
                            | (unsigned)(dx + 63);
        }
    return t;
}

__device__ constexpr OffTable g_off = make_table();

// One block = 256 pixels of one batch image. Whole image + hot table in smem.
__global__ __launch_bounds__(256) void dtm_kernel(const float* __restrict__ xin,
                                                  float* __restrict__ out) {
    __shared__ float          simg[N_PIX];     // 16 KB: full 64x64 image
    __shared__ float          s_d2[STAGE];     // 8 KB: pre-converted d2 (float)
    __shared__ unsigned short s_off[STAGE];    // 4 KB: packed (dy+63)<<8 | (dx+63)
    __shared__ float          sred[256];       // block reduction scratch

    const int tid   = threadIdx.x;
    const int batch = blockIdx.x >> 4;           // 16 blocks per batch
    const int base  = (blockIdx.x & 15) << 8;    // pixel slab start
    const float* img = xin + batch * N_PIX;

    // Cooperative image load (float4) + partial sum for total mass.
    float part = 0.0f;
    const float4* img4 = (const float4*)img;
    #pragma unroll
    for (int j = 0; j < N_PIX / (256 * 4); ++j) {
        float4 v = img4[tid + j * 256];
        ((float4*)simg)[tid + j * 256] = v;
        part += (v.x + v.y) + (v.z + v.w);
    }

    // Stage hot table prefix: split packed word into float d2 + ushort offset.
    #pragma unroll
    for (int j = 0; j < STAGE / 256; ++j) {
        unsigned p = g_off.v[tid + j * 256];
        s_d2[tid + j * 256]  = (float)(p >> 16);
        s_off[tid + j * 256] = (unsigned short)(p & 0xFFFFu);
    }

    sred[tid] = part;
    __syncthreads();

    // Block tree reduction for total mass.
    #pragma unroll
    for (int s = 128; s > 0; s >>= 1) {
        if (tid < s) sred[tid] += sred[tid + s];
        __syncthreads();
    }
    const float total = sred[0];
    const float m     = M0_CONST * total;

    const int i = base + tid;          // pixel index within image
    const int y = i >> 6;
    const int x = i & 63;

    float cum = 0.0f;
    float s   = 0.0f;

    if (total > 0.0f) {
        // Branchless chunked scan over the staged table.
        for (int k = 0; k < STAGE; k += CH) {
            float wv[CH], dv[CH];
            #pragma unroll
            for (int c = 0; c < CH; ++c) {
                const unsigned o  = s_off[k + c];           // broadcast LDS
                const int ny = y + (int)(o >> 8) - 63;
                const int nx = x + (int)(o & 255u) - 63;
                const bool v = ((unsigned)ny < (unsigned)H_DIM) &
                               ((unsigned)nx < (unsigned)W_DIM);
                const int idx = v ? ((ny << 6) | nx) : 0;
                float w = simg[idx];                        // conflict-free LDS
                wv[c] = v ? w : 0.0f;                       // OOB -> exact no-op
                dv[c] = s_d2[k + c];
            }
            #pragma unroll
            for (int c = 0; c < CH; ++c) {
                // Once saturated (cum >= m), eff clamps to 0 -> no-op; no branch.
                const float eff = fmaxf(0.0f, fminf(wv[c], m - cum));
                s = fmaf(eff, dv[c], s);
                cum += wv[c];
            }
            if (__all_sync(0xFFFFFFFFu, cum >= m)) break;   // warp-uniform exit
        }

        // Fallback for pathological inputs (never hit for uniform weights):
        if (!__all_sync(0xFFFFFFFFu, cum >= m)) {
            for (int k = STAGE; k < NOFF; ++k) {
                const unsigned p = g_off.v[k];
                const int ny = y + (int)((p >> 8) & 255u) - 63;
                const int nx = x + (int)(p & 255u) - 63;
                if (((unsigned)ny < (unsigned)H_DIM) &
                    ((unsigned)nx < (unsigned)W_DIM)) {
                    const float w   = simg[(ny << 6) | nx];
                    const float eff = fmaxf(0.0f, fminf(w, m - cum));
                    s = fmaf(eff, (float)(p >> 16), s);
                    cum += w;
                }
                if (__all_sync(0xFFFFFFFFu, cum >= m)) break;
            }
        }
    }

    const float result = (total > 0.0f) ? sqrtf(s / m) : 0.0f;
    out[batch * N_PIX + i] = result;
}

extern "C" void kernel_launch(void* const* d_in, const int* in_sizes, int n_in,
                              void* d_out, int out_size) {
    const float* xin = (const float*)d_in[0];
    float* out = (float*)d_out;
    (void)in_sizes; (void)n_in; (void)out_size;
    dtm_kernel<<<B_DIM * (N_PIX / 256), 256>>>(xin, out);
}

// round 6
// speedup vs baseline: 2.1393x; 1.1357x over previous
#include <cuda_runtime.h>
#include <math.h>

// Problem constants (fixed shapes: x is (8,1,64,64) float32)
#define B_DIM 8
#define H_DIM 64
#define W_DIM 64
#define N_PIX (H_DIM * W_DIM)          // 4096
#define M0_CONST 0.01f

// Offset table: all (dy,dx) in [-63,63]^2 sorted by d2 = dy^2+dx^2 via
// compile-time counting sort. Packed: d2<<16 | (dy+63)<<8 | (dx+63).
#define NOFF (127 * 127)               // 16129
#define MAXD2 (63 * 63 * 2)            // 7938
#define STAGE 1024                     // staged hot prefix (worst-case need ~200)
#define ZSLOT N_PIX                    // smem slot holding 0.0f for OOB lanes

struct OffTable { unsigned int v[NOFF]; };

constexpr OffTable make_table() {
    OffTable t{};
    int bins[MAXD2 + 1] = {};
    for (int dy = -63; dy <= 63; ++dy)
        for (int dx = -63; dx <= 63; ++dx)
            bins[dy * dy + dx * dx]++;
    int acc = 0;
    for (int d = 0; d <= MAXD2; ++d) { int c = bins[d]; bins[d] = acc; acc += c; }
    for (int dy = -63; dy <= 63; ++dy)
        for (int dx = -63; dx <= 63; ++dx) {
            int d2 = dy * dy + dx * dx;
            t.v[bins[d2]++] = ((unsigned)d2 << 16)
                            | ((unsigned)(dy + 63) << 8)
                            | (unsigned)(dx + 63);
        }
    return t;
}

__device__ constexpr OffTable g_off = make_table();

// One block = 256 pixels of one batch image. Image + hot table in smem.
__global__ __launch_bounds__(256) void dtm_kernel(const float* __restrict__ xin,
                                                  float* __restrict__ out) {
    __shared__ __align__(16) float          simg[N_PIX + 4]; // image + zero slot
    __shared__ __align__(16) float          s_d2[STAGE];     // d2 as float
    __shared__ __align__(16) unsigned short s_off[STAGE];    // (dy+63)<<8|(dx+63)
    __shared__ float          swarp[8];                      // per-warp sums

    const int tid   = threadIdx.x;
    const int lane  = tid & 31;
    const int wid   = tid >> 5;
    const int batch = blockIdx.x >> 4;           // 16 blocks per batch
    const int base  = (blockIdx.x & 15) << 8;    // pixel slab start
    const float* img = xin + batch * N_PIX;

    // Cooperative image load (float4) + partial sum for total mass.
    float part = 0.0f;
    const float4* img4 = (const float4*)img;
    #pragma unroll
    for (int j = 0; j < N_PIX / (256 * 4); ++j) {
        float4 v = img4[tid + j * 256];
        ((float4*)simg)[tid + j * 256] = v;
        part += (v.x + v.y) + (v.z + v.w);
    }
    if (tid == 0) simg[ZSLOT] = 0.0f;            // OOB weight slot

    // Stage hot table prefix: float d2 + packed ushort offset.
    #pragma unroll
    for (int j = 0; j < STAGE / 256; ++j) {
        unsigned p = g_off.v[tid + j * 256];
        s_d2[tid + j * 256]  = (float)(p >> 16);
        s_off[tid + j * 256] = (unsigned short)(p & 0xFFFFu);
    }

    // Warp shuffle reduction, then one barrier publishes everything.
    #pragma unroll
    for (int o = 16; o > 0; o >>= 1)
        part += __shfl_xor_sync(0xFFFFFFFFu, part, o);
    if (lane == 0) swarp[wid] = part;
    __syncthreads();

    float total = 0.0f;
    {
        float4 a = ((const float4*)swarp)[0];
        float4 b = ((const float4*)swarp)[1];
        total = ((a.x + a.y) + (a.z + a.w)) + ((b.x + b.y) + (b.z + b.w));
    }
    const float m = M0_CONST * total;

    const int i = base + tid;          // pixel index within image
    const int y = i >> 6;
    const int x = i & 63;
    // Packed base: Qm = basep + e  gives ((y+dy)<<8)+(x+dx); valid iff the
    // masked bits (incl. sign / carry spill) are all zero.
    const int basep = ((y << 8) | x) - 0x3F3F;

    float cum = 0.0f;
    float s   = 0.0f;

    if (total > 0.0f) {
        for (int k = 0; k < STAGE; k += 8) {
            const uint4  ov = *reinterpret_cast<const uint4*>(&s_off[k]);
            const float4 dA = *reinterpret_cast<const float4*>(&s_d2[k]);
            const float4 dB = *reinterpret_cast<const float4*>(&s_d2[k + 4]);
            const unsigned eo[8] = { ov.x & 0xFFFFu, ov.x >> 16,
                                     ov.y & 0xFFFFu, ov.y >> 16,
                                     ov.z & 0xFFFFu, ov.z >> 16,
                                     ov.w & 0xFFFFu, ov.w >> 16 };
            const float dd[8] = { dA.x, dA.y, dA.z, dA.w,
                                  dB.x, dB.y, dB.z, dB.w };
            float wv[8];
            #pragma unroll
            for (int c = 0; c < 8; ++c) {
                const int Qm = basep + (int)eo[c];
                const bool valid = (Qm & ~0x3F3F) == 0;
                const int idx = ((Qm >> 2) & 0x0FC0) | (Qm & 0x3F);
                wv[c] = simg[valid ? idx : ZSLOT];
            }
            #pragma unroll
            for (int c = 0; c < 8; ++c) {
                // After saturation eff clamps to 0 -> exact no-op, no branch.
                const float eff = fmaxf(0.0f, fminf(wv[c], m - cum));
                s = fmaf(eff, dd[c], s);
                cum += wv[c];
            }
            if (__all_sync(0xFFFFFFFFu, cum >= m)) break;   // warp-uniform exit
        }

        // Fallback for pathological inputs (never hit for uniform weights).
        if (!__all_sync(0xFFFFFFFFu, cum >= m)) {
            for (int k = STAGE; k < NOFF; ++k) {
                const unsigned p = g_off.v[k];
                const int Qm = basep + (int)(p & 0xFFFFu);
                if ((Qm & ~0x3F3F) == 0) {
                    const int idx = ((Qm >> 2) & 0x0FC0) | (Qm & 0x3F);
                    const float w   = simg[idx];
                    const float eff = fmaxf(0.0f, fminf(w, m - cum));
                    s = fmaf(eff, (float)(p >> 16), s);
                    cum += w;
                }
                if (__all_sync(0xFFFFFFFFu, cum >= m)) break;
            }
        }
    }

    const float result = (total > 0.0f) ? sqrtf(s / m) : 0.0f;
    out[batch * N_PIX + i] = result;
}

extern "C" void kernel_launch(void* const* d_in, const int* in_sizes, int n_in,
                              void* d_out, int out_size) {
    const float* xin = (const float*)d_in[0];
    float* out = (float*)d_out;
    (void)in_sizes; (void)n_in; (void)out_size;
    dtm_kernel<<<B_DIM * (N_PIX / 256), 256>>>(xin, out);
}

// round 8
// speedup vs baseline: 2.2185x; 1.0370x over previous
#include <cuda_runtime.h>
#include <math.h>

// Problem constants (fixed shapes: x is (8,1,64,64) float32)
#define B_DIM 8
#define H_DIM 64
#define W_DIM 64
#define N_PIX (H_DIM * W_DIM)          // 4096
#define M0_CONST 0.01f

// Offset table: all (dy,dx) in [-63,63]^2 sorted by d2 = dy^2+dx^2 via
// compile-time counting sort. Packed: d2<<16 | (dy+63)<<8 | (dx+63).
#define NOFF (127 * 127)               // 16129
#define MAXD2 (63 * 63 * 2)            // 7938
#define ALLOC 768                      // staged entries (3 LDG rounds, no guard)
#define STAGE 704                      // main-loop bound (ALLOC - 2*CH headroom)
#define CH 16                          // entries per pipeline stage
#define ZSLOT N_PIX                    // smem slot holding 0.0f for OOB lanes

struct OffTable { unsigned int v[NOFF]; };

constexpr OffTable make_table() {
    OffTable t{};
    int bins[MAXD2 + 1] = {};
    for (int dy = -63; dy <= 63; ++dy)
        for (int dx = -63; dx <= 63; ++dx)
            bins[dy * dy + dx * dx]++;
    int acc = 0;
    for (int d = 0; d <= MAXD2; ++d) { int c = bins[d]; bins[d] = acc; acc += c; }
    for (int dy = -63; dy <= 63; ++dy)
        for (int dx = -63; dx <= 63; ++dx) {
            int d2 = dy * dy + dx * dx;
            t.v[bins[d2]++] = ((unsigned)d2 << 16)
                            | ((unsigned)(dy + 63) << 8)
                            | (unsigned)(dx + 63);
        }
    return t;
}

__device__ constexpr OffTable g_off = make_table();

// Gather one 16-entry chunk: table reads are vectorized (LDS.128), weight
// addresses depend only on the static table -> fully independent of the FP
// chain, so chunks can be prefetched ahead of the mass accumulation.
__device__ __forceinline__ void load16(int k, int basep,
                                       const float* __restrict__ simg,
                                       const unsigned short* __restrict__ s_off,
                                       const float* __restrict__ s_d2,
                                       float* wv, float* dv) {
    const uint4 o0 = *reinterpret_cast<const uint4*>(s_off + k);
    const uint4 o1 = *reinterpret_cast<const uint4*>(s_off + k + 8);
    const float4 dA = *reinterpret_cast<const float4*>(s_d2 + k);
    const float4 dB = *reinterpret_cast<const float4*>(s_d2 + k + 4);
    const float4 dC = *reinterpret_cast<const float4*>(s_d2 + k + 8);
    const float4 dD = *reinterpret_cast<const float4*>(s_d2 + k + 12);
    const unsigned ow[8] = { o0.x, o0.y, o0.z, o0.w, o1.x, o1.y, o1.z, o1.w };
    #pragma unroll
    for (int j = 0; j < 8; ++j) {
        const int Qa = basep + (int)(ow[j] & 0xFFFFu);
        const int Qb = basep + (int)(ow[j] >> 16);
        const int ia = Qa - (Qa >> 8) * 192;      // ny*64+nx (SHF+IMAD)
        const int ib = Qb - (Qb >> 8) * 192;
        wv[2 * j]     = simg[((Qa & ~0x3F3F) == 0) ? ia : ZSLOT];
        wv[2 * j + 1] = simg[((Qb & ~0x3F3F) == 0) ? ib : ZSLOT];
    }
    dv[0] = dA.x; dv[1] = dA.y; dv[2]  = dA.z; dv[3]  = dA.w;
    dv[4] = dB.x; dv[5] = dB.y; dv[6]  = dB.z; dv[7]  = dB.w;
    dv[8] = dC.x; dv[9] = dC.y; dv[10] = dC.z; dv[11] = dC.w;
    dv[12] = dD.x; dv[13] = dD.y; dv[14] = dD.z; dv[15] = dD.w;
}

// Consume 16 entries. rem = m - cum is the carried state; per-group-of-4
// register prefix sums keep the serial dependence to one FADD per group.
__device__ __forceinline__ void proc16(const float* wv, const float* dv,
                                       float& rem, float& s0, float& s1,
                                       float& s2, float& s3) {
    float r = rem;
    #pragma unroll
    for (int g = 0; g < 4; ++g) {
        const float* w = wv + 4 * g;
        const float* d = dv + 4 * g;
        const float p1 = w[0];
        const float p2 = p1 + w[1];
        const float p3 = p2 + w[2];
        const float gs = p3 + w[3];
        const float e0 = fmaxf(0.f, fminf(w[0], r));
        const float e1 = fmaxf(0.f, fminf(w[1], r - p1));
        const float e2 = fmaxf(0.f, fminf(w[2], r - p2));
        const float e3 = fmaxf(0.f, fminf(w[3], r - p3));
        s0 = fmaf(e0, d[0], s0);
        s1 = fmaf(e1, d[1], s1);
        s2 = fmaf(e2, d[2], s2);
        s3 = fmaf(e3, d[3], s3);
        r -= gs;
    }
    rem = r;
}

// One block = 256 pixels of one batch image. Image + hot table in smem.
__global__ __launch_bounds__(256) void dtm_kernel(const float* __restrict__ xin,
                                                  float* __restrict__ out) {
    __shared__ __align__(16) float          simg[N_PIX + 4]; // image + zero slot
    __shared__ __align__(16) float          s_d2[ALLOC];     // d2 as float
    __shared__ __align__(16) unsigned short s_off[ALLOC];    // (dy+63)<<8|(dx+63)
    __shared__ float          swarp[8];                      // per-warp sums

    const int tid   = threadIdx.x;
    const int lane  = tid & 31;
    const int wid   = tid >> 5;
    const int batch = blockIdx.x >> 4;           // 16 blocks per batch
    const int base  = (blockIdx.x & 15) << 8;    // pixel slab start
    const float* img = xin + batch * N_PIX;

    // Cooperative image load (float4) + partial sum for total mass.
    float part = 0.0f;
    const float4* img4 = (const float4*)img;
    #pragma unroll
    for (int j = 0; j < N_PIX / (256 * 4); ++j) {
        float4 v = img4[tid + j * 256];
        ((float4*)simg)[tid + j * 256] = v;
        part += (v.x + v.y) + (v.z + v.w);
    }
    if (tid == 0) simg[ZSLOT] = 0.0f;            // OOB weight slot

    // Stage hot table prefix: float d2 + packed ushort offset.
    #pragma unroll
    for (int j = 0; j < ALLOC / 256; ++j) {
        unsigned p = g_off.v[tid + j * 256];
        s_d2[tid + j * 256]  = (float)(p >> 16);
        s_off[tid + j * 256] = (unsigned short)(p & 0xFFFFu);
    }

    // Warp shuffle reduction, then one barrier publishes everything.
    #pragma unroll
    for (int o = 16; o > 0; o >>= 1)
        part += __shfl_xor_sync(0xFFFFFFFFu, part, o);
    if (lane == 0) swarp[wid] = part;
    __syncthreads();

    float total;
    {
        float4 a = ((const float4*)swarp)[0];
        float4 b = ((const float4*)swarp)[1];
        total = ((a.x + a.y) + (a.z + a.w)) + ((b.x + b.y) + (b.z + b.w));
    }
    const float m = M0_CONST * total;

    const int i = base + tid;          // pixel index within image
    const int y = i >> 6;
    const int x = i & 63;
    // Packed base: Qm = basep + e gives ((y+dy)<<8)+(x+dx); valid iff the
    // masked bits (sign / carry spill included) are all zero.
    const int basep = ((y << 8) | x) - 0x3F3F;

    float rem = m;                     // m - cum, carried
    float s0 = 0.f, s1 = 0.f, s2 = 0.f, s3 = 0.f;
    bool alldone = false;
    int k = 0;

    if (m > 0.0f) {
        float wA[CH], dA[CH], wB[CH], dB[CH];
        load16(0, basep, simg, s_off, s_d2, wA, dA);
        // 2-stage software pipeline: prefetch next chunk's gathers before
        // running the current chunk's mass accumulation.
        for (;;) {
            load16(k + CH, basep, simg, s_off, s_d2, wB, dB);
            proc16(wA, dA, rem, s0, s1, s2, s3);
            k += CH;
            if (__all_sync(0xFFFFFFFFu, rem <= 0.0f)) { alldone = true; break; }
            if (k >= STAGE) break;
            load16(k + CH, basep, simg, s_off, s_d2, wA, dA);
            proc16(wB, dB, rem, s0, s1, s2, s3);
            k += CH;
            if (__all_sync(0xFFFFFFFFu, rem <= 0.0f)) { alldone = true; break; }
            if (k >= STAGE) break;
        }

        // Fallback for pathological inputs (never hit for uniform weights).
        if (!alldone) {
            for (; k < NOFF; ++k) {
                const unsigned p = g_off.v[k];
                const int Qm = basep + (int)(p & 0xFFFFu);
                if ((Qm & ~0x3F3F) == 0) {
                    const int idx = Qm - (Qm >> 8) * 192;
                    const float w   = simg[idx];
                    const float eff = fmaxf(0.f, fminf(w, rem));
                    s0 = fmaf(eff, (float)(p >> 16), s0);
                    rem -= w;
                }
                if (__all_sync(0xFFFFFFFFu, rem <= 0.0f)) break;
            }
        }
    }

    const float s = (s0 + s1) + (s2 + s3);
    const float result = (total > 0.0f) ? sqrtf(s / m) : 0.0f;
    out[batch * N_PIX + i] = result;
}

extern "C" void kernel_launch(void* const* d_in, const int* in_sizes, int n_in,
                              void* d_out, int out_size) {
    const float* xin = (const float*)d_in[0];
    float* out = (float*)d_out;
    (void)in_sizes; (void)n_in; (void)out_size;
    dtm_kernel<<<B_DIM * (N_PIX / 256), 256>>>(xin, out);
}